// round 14
// baseline (speedup 1.0000x reference)
#include <cuda_runtime.h>
#include <math.h>

#define N_SRC   40000
#define L_TGT   4096
#define NSPLIT  37
#define CHUNK   1082
#define TILE    192               /* 12 k-chunks of 16 */
#define NT      128
#define TGB     256               /* targets per block: 4 warps x 64 */
#define KNEG    (-0.5770780163555852f)
#define EPSC    0.01f

typedef unsigned long long u64;

/* ---------------- packed f32x2 helpers ---------------- */
__device__ __forceinline__ u64 pk(float lo, float hi) {
    u64 r; asm("mov.b64 %0, {%1, %2};" : "=l"(r) : "f"(lo), "f"(hi)); return r;
}
__device__ __forceinline__ void upk(u64 v, float& lo, float& hi) {
    asm("mov.b64 {%0, %1}, %2;" : "=f"(lo), "=f"(hi) : "l"(v));
}
__device__ __forceinline__ u64 fma2(u64 a, u64 b, u64 c) {
    u64 d; asm("fma.rn.f32x2 %0, %1, %2, %3;" : "=l"(d) : "l"(a), "l"(b), "l"(c)); return d;
}
__device__ __forceinline__ u64 mul2(u64 a, u64 b) {
    u64 d; asm("mul.rn.f32x2 %0, %1, %2;" : "=l"(d) : "l"(a), "l"(b)); return d;
}
__device__ __forceinline__ u64 add2(u64 a, u64 b) {
    u64 d; asm("add.rn.f32x2 %0, %1, %2;" : "=l"(d) : "l"(a), "l"(b)); return d;
}
__device__ __forceinline__ float sqrt_ap(float x) {
    float r; asm("sqrt.approx.f32 %0, %1;" : "=f"(r) : "f"(x)); return r;
}
__device__ __forceinline__ float ex2_ap(float x) {
    float r; asm("ex2.approx.f32 %0, %1;" : "=f"(r) : "f"(x)); return r;
}
__device__ __forceinline__ float norm2_ref(float x, float y, float z) {
    return __fadd_rn(__fadd_rn(__fmul_rn(x, x), __fmul_rn(y, y)), __fmul_rn(z, z));
}
__device__ __forceinline__ unsigned int smem_u32(const void* p) {
    unsigned int a;
    asm("{ .reg .u64 t; cvta.to.shared.u64 t, %1; cvt.u32.u64 %0, t; }" : "=r"(a) : "l"(p));
    return a;
}
__device__ __forceinline__ unsigned short bf16_of(float x) {
    unsigned short h; asm("cvt.rn.bf16.f32 %0, %1;" : "=h"(h) : "f"(x)); return h;
}
__device__ __forceinline__ void sts16(unsigned int a, unsigned short v) {
    asm volatile("st.shared.b16 [%0], %1;" :: "r"(a), "h"(v));
}
__device__ __forceinline__ unsigned int lds32(unsigned int a) {
    unsigned int v; asm volatile("ld.shared.b32 %0, [%1];" : "=r"(v) : "r"(a)); return v;
}
__device__ __forceinline__ float ldsf(unsigned int a) {
    float v; asm volatile("ld.shared.f32 %0, [%1];" : "=f"(v) : "r"(a)); return v;
}
__device__ __forceinline__ void stsv2f(unsigned int a, float x, float y) {
    asm volatile("st.shared.v2.f32 [%0], {%1, %2};" :: "r"(a), "f"(x), "f"(y));
}
__device__ __forceinline__ void ldmat4t(unsigned int& r0, unsigned int& r1,
                                        unsigned int& r2, unsigned int& r3, unsigned int a) {
    asm volatile("ldmatrix.sync.aligned.m8n8.x4.trans.shared.b16 {%0,%1,%2,%3}, [%4];"
                 : "=r"(r0), "=r"(r1), "=r"(r2), "=r"(r3) : "r"(a));
}
__device__ __forceinline__ void mma_bf16(float* d, unsigned int a0, unsigned int a1,
                                         unsigned int a2, unsigned int a3,
                                         unsigned int b0, unsigned int b1) {
    asm volatile("mma.sync.aligned.m16n8k16.row.col.f32.bf16.bf16.f32 "
                 "{%0,%1,%2,%3}, {%4,%5,%6,%7}, {%8,%9}, {%0,%1,%2,%3};"
                 : "+f"(d[0]), "+f"(d[1]), "+f"(d[2]), "+f"(d[3])
                 : "r"(a0), "r"(a1), "r"(a2), "r"(a3), "r"(b0), "r"(b1));
}

/* ---------------- scratch: partials [row][split][14] ---------------- */
__device__ u64  d_part[L_TGT * NSPLIT * 14];
__device__ int2 d_pidx[L_TGT * NSPLIT];

__global__ void dummy1_kernel() {}
__global__ void dummy2_kernel() {}
__global__ void dummy3_kernel() {}

/* smem layout (40960 B):
   [0,6144)      shgp  : TILE ulonglong2 x2 (argmin pairs)
   [6144,12288)  shsp  : rbf pairs
   [12288,24576) sfT   : 2 sides x 16 rows x TILE bf16 (features^T, row 12 = ones)
   [24576,40960) swb   : 4 warps x 2 sides x 16k x 64m bf16 (w staging / epi scratch) */
#define OFF_SP 6144
#define OFF_SF 12288
#define SFP    (TILE * 2)       /* 384 B row pitch */
#define OFF_WB 24576

__global__ void __launch_bounds__(NT, 4)
pass1_kernel(const float* __restrict__ locs_left, const float* __restrict__ locs_right,
             const float* __restrict__ g1_pos, const float* __restrict__ g2_pos,
             const float* __restrict__ s1_verts, const float* __restrict__ s2_verts,
             const float* __restrict__ s1_x, const float* __restrict__ s2_x) {
    __shared__ __align__(16) unsigned char smraw[40960];
    ulonglong2* shgp = (ulonglong2*)smraw;
    ulonglong2* shsp = (ulonglong2*)(smraw + OFF_SP);
    const unsigned int sb   = smem_u32(smraw);
    const unsigned int sfL  = sb + OFF_SF;
    const unsigned int sfR  = sfL + 16 * SFP;
    const int tid  = threadIdx.x;
    const int wid  = tid >> 5;
    const int lane = tid & 31;
    const unsigned int wbL = sb + OFF_WB + wid * 4096;
    const unsigned int wbR = wbL + 2048;

    const int split = blockIdx.y;
    const int base  = split * CHUNK;
    const int cnt   = min(CHUNK, N_SRC - base);
    const int rowbase = blockIdx.x * TGB + wid * 64;
    const float INF = __int_as_float(0x7F800000);

    /* ldmatrix lane base (trans, [k][m] layout, row pitch 128B) */
    const unsigned int krow  = (unsigned int)((lane & 7) + ((lane >> 4) << 3));
    const unsigned int mhalf = (unsigned int)(((lane >> 3) & 1) * 8);
    const unsigned int aLb = wbL + krow * 128 + mhalf * 2;
    const unsigned int aRb = wbR + krow * 128 + mhalf * 2;
    /* w staging addresses for this thread's 2 targets (m = lane, lane+32) */
    const unsigned int wsL0 = wbL + lane * 2, wsL1 = wbL + (lane + 32) * 2;
    const unsigned int wsR0 = wbR + lane * 2, wsR1 = wbR + (lane + 32) * 2;

    /* target constants (targets: rowbase+lane, rowbase+lane+32) */
    u64 txp[2], typ[2], tzp[2], sap[2];
#pragma unroll
    for (int u = 0; u < 2; u++) {
        int l = rowbase + lane + u * 32;
        float tlx = locs_left[3*l],  tly = locs_left[3*l+1],  tlz = locs_left[3*l+2];
        float trx = locs_right[3*l], tryy = locs_right[3*l+1], trz = locs_right[3*l+2];
        txp[u] = pk(tlx, trx); typ[u] = pk(tly, tryy); tzp[u] = pk(tlz, trz);
        sap[u] = pk(norm2_ref(tlx, tly, tlz), norm2_ref(trx, tryy, trz));
    }
    const u64 NEG2P = pk(-2.0f, -2.0f);
    const u64 KNEG2 = pk(KNEG, KNEG);

    float bestL[2] = { 3.4e38f, 3.4e38f }, bestR[2] = { 3.4e38f, 3.4e38f };
    int   bidxL[2] = { 0, 0 }, bidxR[2] = { 0, 0 };
    float dL[4][2][4], dR[4][2][4];
#pragma unroll
    for (int mt = 0; mt < 4; mt++)
#pragma unroll
        for (int nt = 0; nt < 2; nt++)
#pragma unroll
            for (int e = 0; e < 4; e++) { dL[mt][nt][e] = 0.f; dR[mt][nt][e] = 0.f; }

    for (int t = 0; t < cnt; t += TILE) {
        const int m = min(TILE, cnt - t);
        const int tbase = base + t;
        __syncthreads();
        /* ---- fill ---- */
        for (int i = tid; i < TILE; i += NT) {
            ulonglong2 v;
            if (i < m) {
                const int idx = tbase + i;
                float cx = g1_pos[3*idx], cy = g1_pos[3*idx+1], cz = g1_pos[3*idx+2];
                float dx = g2_pos[3*idx], dy = g2_pos[3*idx+1], dz = g2_pos[3*idx+2];
                v.x = pk(cx, dx); v.y = pk(cy, dy); shgp[2*i] = v;
                v.x = pk(cz, dz); v.y = pk(norm2_ref(cx,cy,cz), norm2_ref(dx,dy,dz));
                shgp[2*i+1] = v;
                float ax = s1_verts[3*idx], ay = s1_verts[3*idx+1], az = s1_verts[3*idx+2];
                float bx = s2_verts[3*idx], by = s2_verts[3*idx+1], bz = s2_verts[3*idx+2];
                v.x = pk(ax, bx); v.y = pk(ay, by); shsp[2*i] = v;
                v.x = pk(az, bz); v.y = pk(norm2_ref(ax,ay,az), norm2_ref(bx,by,bz));
                shsp[2*i+1] = v;
                const float4* f1v = (const float4*)(s1_x + 12 * idx);
                const float4* f2v = (const float4*)(s2_x + 12 * idx);
#pragma unroll
                for (int q = 0; q < 3; q++) {
                    float4 a = f1v[q], b = f2v[q];
                    sts16(sfL + (q*4+0)*SFP + i*2, bf16_of(a.x));
                    sts16(sfL + (q*4+1)*SFP + i*2, bf16_of(a.y));
                    sts16(sfL + (q*4+2)*SFP + i*2, bf16_of(a.z));
                    sts16(sfL + (q*4+3)*SFP + i*2, bf16_of(a.w));
                    sts16(sfR + (q*4+0)*SFP + i*2, bf16_of(b.x));
                    sts16(sfR + (q*4+1)*SFP + i*2, bf16_of(b.y));
                    sts16(sfR + (q*4+2)*SFP + i*2, bf16_of(b.z));
                    sts16(sfR + (q*4+3)*SFP + i*2, bf16_of(b.w));
                }
                sts16(sfL + 12*SFP + i*2, (unsigned short)0x3F80u);
                sts16(sfR + 12*SFP + i*2, (unsigned short)0x3F80u);
            } else {
                v.x = pk(0.f, 0.f); v.y = pk(0.f, 0.f);
                shgp[2*i] = v; shsp[2*i] = v;
                v.y = pk(INF, INF);
                shgp[2*i+1] = v; shsp[2*i+1] = v;
#pragma unroll
                for (int q = 0; q < 12; q++) {
                    sts16(sfL + q*SFP + i*2, 0); sts16(sfR + q*SFP + i*2, 0);
                }
                sts16(sfL + 12*SFP + i*2, 0); sts16(sfR + 12*SFP + i*2, 0);
            }
#pragma unroll
            for (int q = 13; q < 16; q++) {
                sts16(sfL + q*SFP + i*2, 0); sts16(sfR + q*SFP + i*2, 0);
            }
        }
        __syncthreads();

        const int nch = (m + 15) >> 4;
        for (int c = 0; c < nch; c++) {
            const int kbase = c * 16;
            /* ---- scalar: distances, argmin, w -> staging ---- */
#pragma unroll 4
            for (int jj = 0; jj < 16; jj++) {
                const int j = kbase + jj;
                const int src = tbase + j;
                const ulonglong2 g0 = shgp[2*j], g1 = shgp[2*j+1];
                const ulonglong2 s0 = shsp[2*j], s1 = shsp[2*j+1];
#pragma unroll
                for (int u = 0; u < 2; u++) {
                    u64 dot = fma2(tzp[u], g1.x, fma2(typ[u], g0.y, mul2(txp[u], g0.x)));
                    u64 sab = add2(sap[u], g1.y);
                    u64 d2p = fma2(dot, NEG2P, sab);
                    float d2L, d2R; upk(d2p, d2L, d2R);
                    if (d2L < bestL[u]) { bestL[u] = d2L; bidxL[u] = src; }
                    if (d2R < bestR[u]) { bestR[u] = d2R; bidxR[u] = src; }

                    u64 rdot = fma2(tzp[u], s1.x, fma2(typ[u], s0.y, mul2(txp[u], s0.x)));
                    u64 rsab = add2(sap[u], s1.y);
                    u64 r2p  = fma2(rdot, NEG2P, rsab);
                    float r2L, r2R; upk(r2p, r2L, r2R);
                    u64 sq = mul2(pk(sqrt_ap(r2L), sqrt_ap(r2R)), KNEG2);
                    float eL, eR; upk(sq, eL, eR);
                    float wl = ex2_ap(eL), wr = ex2_ap(eR);
                    if (u == 0) {
                        sts16(wsL0 + jj*128, bf16_of(wl));
                        sts16(wsR0 + jj*128, bf16_of(wr));
                    } else {
                        sts16(wsL1 + jj*128, bf16_of(wl));
                        sts16(wsR1 + jj*128, bf16_of(wr));
                    }
                }
            }
            __syncwarp();
            /* ---- B fragments: sfT[n][k], b0 k=(lane%4)*2, n=lane/4 ---- */
            unsigned int bL[2][2], bR[2][2];
#pragma unroll
            for (int nt = 0; nt < 2; nt++) {
                unsigned int off = ((lane >> 2) + nt*8) * SFP + (kbase + (lane & 3)*2) * 2;
                bL[nt][0] = lds32(sfL + off); bL[nt][1] = lds32(sfL + off + 16);
                bR[nt][0] = lds32(sfR + off); bR[nt][1] = lds32(sfR + off + 16);
            }
            /* ---- A fragments + MMA ---- */
#pragma unroll
            for (int mt = 0; mt < 4; mt++) {
                unsigned int a0, a1, a2, a3;
                ldmat4t(a0, a1, a2, a3, aLb + mt * 32);
                mma_bf16(dL[mt][0], a0, a1, a2, a3, bL[0][0], bL[0][1]);
                mma_bf16(dL[mt][1], a0, a1, a2, a3, bL[1][0], bL[1][1]);
                ldmat4t(a0, a1, a2, a3, aRb + mt * 32);
                mma_bf16(dR[mt][0], a0, a1, a2, a3, bR[0][0], bR[0][1]);
                mma_bf16(dR[mt][1], a0, a1, a2, a3, bR[1][0], bR[1][1]);
            }
        }
    }

    /* ---- epilogue: stage D per mt, gather per target, write partials ---- */
    const unsigned int stgL = wbL;            /* reuse warp scratch */
    const unsigned int stgR = wbL + 1024;
    const int r  = lane >> 2;
    const int cb = (lane & 3) * 2;
#pragma unroll
    for (int mt = 0; mt < 4; mt++) {
        __syncwarp();
#pragma unroll
        for (int nt = 0; nt < 2; nt++) {
            stsv2f(stgL + ((r    )*16 + nt*8 + cb)*4, dL[mt][nt][0], dL[mt][nt][1]);
            stsv2f(stgL + ((r + 8)*16 + nt*8 + cb)*4, dL[mt][nt][2], dL[mt][nt][3]);
            stsv2f(stgR + ((r    )*16 + nt*8 + cb)*4, dR[mt][nt][0], dR[mt][nt][1]);
            stsv2f(stgR + ((r + 8)*16 + nt*8 + cb)*4, dR[mt][nt][2], dR[mt][nt][3]);
        }
        __syncwarp();
        if (lane < 16) {
            const int row = rowbase + mt * 16 + lane;
            u64* pb = &d_part[(row * NSPLIT + split) * 14];
#pragma unroll
            for (int k = 0; k < 13; k++) {
                float vL = ldsf(stgL + (lane*16 + k)*4);
                float vR = ldsf(stgR + (lane*16 + k)*4);
                pb[k] = pk(vL, vR);
            }
        }
    }
#pragma unroll
    for (int u = 0; u < 2; u++) {
        const int row = rowbase + lane + u * 32;
        const int o = row * NSPLIT + split;
        d_part[o * 14 + 13] = pk(bestL[u], bestR[u]);
        d_pidx[o] = make_int2(bidxL[u], bidxR[u]);
    }
}

/* ------------- pass2: warp per row (R13, unchanged) ------------- */
#define P2NT 128
__global__ void __launch_bounds__(P2NT)
pass2_kernel(const float* __restrict__ g1_x, const float* __restrict__ g2_x,
             const float* __restrict__ W1, const float* __restrict__ b1,
             const float* __restrict__ W2, const float* __restrict__ b2,
             float* __restrict__ out) {
    __shared__ float sW1[2500], sb1[50], sW2[50];
    __shared__ float sx[P2NT / 32][52];
    for (int i = threadIdx.x; i < 2500; i += P2NT) sW1[i] = W1[i];
    if (threadIdx.x < 50) { sb1[threadIdx.x] = b1[threadIdx.x]; sW2[threadIdx.x] = W2[threadIdx.x]; }
    __syncthreads();

    const int w    = threadIdx.x >> 5;
    const int lane = threadIdx.x & 31;
    const int row  = blockIdx.x * (P2NT / 32) + w;

    float bestL = 3.4e38f, bestR = 3.4e38f;
    int bidxL = 0, bidxR = 0;
    float nL = 0.f, nR = 0.f;
    float aL[12], aR[12];
#pragma unroll
    for (int k = 0; k < 12; k++) { aL[k] = 0.f; aR[k] = 0.f; }

#pragma unroll
    for (int half = 0; half < 2; half++) {
        int s = lane + half * 32;
        if (s < NSPLIT) {
            const int o = row * NSPLIT + s;
            const u64* pb = &d_part[o * 14];
#pragma unroll
            for (int k = 0; k < 12; k++) {
                float xk, yk; upk(pb[k], xk, yk);
                aL[k] += xk; aR[k] += yk;
            }
            float pnL, pnR; upk(pb[12], pnL, pnR);
            nL += pnL; nR += pnR;
            float bL, bR; upk(pb[13], bL, bR);
            int2 bi = d_pidx[o];
            if (bL < bestL) { bestL = bL; bidxL = bi.x; }
            if (bR < bestR) { bestR = bR; bidxR = bi.y; }
        }
    }
#pragma unroll
    for (int m = 16; m >= 1; m >>= 1) {
        float obL = __shfl_xor_sync(0xffffffffu, bestL, m);
        int   oiL = __shfl_xor_sync(0xffffffffu, bidxL, m);
        if (obL < bestL || (obL == bestL && oiL < bidxL)) { bestL = obL; bidxL = oiL; }
        float obR = __shfl_xor_sync(0xffffffffu, bestR, m);
        int   oiR = __shfl_xor_sync(0xffffffffu, bidxR, m);
        if (obR < bestR || (obR == bestR && oiR < bidxR)) { bestR = obR; bidxR = oiR; }
        nL += __shfl_xor_sync(0xffffffffu, nL, m);
        nR += __shfl_xor_sync(0xffffffffu, nR, m);
#pragma unroll
        for (int k = 0; k < 12; k++) {
            aL[k] += __shfl_xor_sync(0xffffffffu, aL[k], m);
            aR[k] += __shfl_xor_sync(0xffffffffu, aR[k], m);
        }
    }
    nL += EPSC; nR += EPSC;

    if (lane == 0) {
        const float* gl = &g1_x[bidxL * 12];
        const float* gr = &g2_x[bidxR * 12];
        float invL = 1.f / nL, invR = 1.f / nR;
#pragma unroll
        for (int k = 0; k < 12; k++) {
            sx[w][k]      = gl[k];
            sx[w][12 + k] = aL[k] * invL;
            sx[w][25 + k] = gr[k];
            sx[w][37 + k] = aR[k] * invR;
        }
        sx[w][24] = tanhf(nL);
        sx[w][49] = tanhf(nR);
    }
    __syncwarp();

    const int j1 = lane;
    const int j2 = lane + 32;
    float h1 = sb1[j1];
    float h2 = (j2 < 50) ? sb1[j2] : 0.f;
#pragma unroll 10
    for (int i = 0; i < 50; i++) {
        float xi = sx[w][i];
        h1 = fmaf(xi, sW1[i * 50 + j1], h1);
        if (j2 < 50) h2 = fmaf(xi, sW1[i * 50 + j2], h2);
    }
    float val = (j1 < 50 ? fmaxf(h1, 0.f) * sW2[j1] : 0.f)
              + (j2 < 50 ? fmaxf(h2, 0.f) * sW2[j2] : 0.f);
#pragma unroll
    for (int m = 16; m >= 1; m >>= 1)
        val += __shfl_xor_sync(0xffffffffu, val, m);
    if (lane == 0) out[row] = val + b2[0];
}

extern "C" void kernel_launch(void* const* d_in, const int* in_sizes, int n_in,
                              void* d_out, int out_size) {
    const float* locs_left  = (const float*)d_in[0];
    const float* locs_right = (const float*)d_in[1];
    const float* g1_pos     = (const float*)d_in[2];
    const float* g1_x       = (const float*)d_in[3];
    const float* g2_pos     = (const float*)d_in[4];
    const float* g2_x       = (const float*)d_in[5];
    const float* s1_verts   = (const float*)d_in[6];
    const float* s1_x       = (const float*)d_in[7];
    const float* s2_verts   = (const float*)d_in[8];
    const float* s2_x       = (const float*)d_in[9];
    const float* W1         = (const float*)d_in[10];
    const float* b1         = (const float*)d_in[11];
    const float* W2         = (const float*)d_in[12];
    const float* b2         = (const float*)d_in[13];
    float* out = (float*)d_out;

    dummy1_kernel<<<1, 32>>>();
    dummy2_kernel<<<1, 32>>>();
    dummy3_kernel<<<1, 32>>>();
    dim3 grid1(L_TGT / TGB, NSPLIT);   /* 16 x 37 = 592 = 148 SMs * occ 4 */
    pass1_kernel<<<grid1, NT>>>(locs_left, locs_right, g1_pos, g2_pos,
                                s1_verts, s2_verts, s1_x, s2_x);
    pass2_kernel<<<L_TGT / (P2NT / 32), P2NT>>>(g1_x, g2_x, W1, b1, W2, b2, out);
}

// round 15
// speedup vs baseline: 1.4371x; 1.4371x over previous
#include <cuda_runtime.h>
#include <math.h>

#define N_SRC   40000
#define L_TGT   4096
#define NSPLIT  37
#define CHUNK   1082
#define TILE    192               /* 12 k-chunks of 16 */
#define NT      128
#define TGB     256               /* 4 warps x 64 targets */
#define KNEG    (-0.5770780163555852f)
#define EPSC    0.01f

typedef unsigned long long u64;

/* ---------------- helpers ---------------- */
__device__ __forceinline__ u64 pk(float lo, float hi) {
    u64 r; asm("mov.b64 %0, {%1, %2};" : "=l"(r) : "f"(lo), "f"(hi)); return r;
}
__device__ __forceinline__ void upk(u64 v, float& lo, float& hi) {
    asm("mov.b64 {%0, %1}, %2;" : "=f"(lo), "=f"(hi) : "l"(v));
}
__device__ __forceinline__ u64 fma2(u64 a, u64 b, u64 c) {
    u64 d; asm("fma.rn.f32x2 %0, %1, %2, %3;" : "=l"(d) : "l"(a), "l"(b), "l"(c)); return d;
}
__device__ __forceinline__ u64 mul2(u64 a, u64 b) {
    u64 d; asm("mul.rn.f32x2 %0, %1, %2;" : "=l"(d) : "l"(a), "l"(b)); return d;
}
__device__ __forceinline__ u64 add2(u64 a, u64 b) {
    u64 d; asm("add.rn.f32x2 %0, %1, %2;" : "=l"(d) : "l"(a), "l"(b)); return d;
}
__device__ __forceinline__ float sqrt_ap(float x) {
    float r; asm("sqrt.approx.f32 %0, %1;" : "=f"(r) : "f"(x)); return r;
}
__device__ __forceinline__ float ex2_ap(float x) {
    float r; asm("ex2.approx.f32 %0, %1;" : "=f"(r) : "f"(x)); return r;
}
__device__ __forceinline__ float norm2_ref(float x, float y, float z) {
    return __fadd_rn(__fadd_rn(__fmul_rn(x, x), __fmul_rn(y, y)), __fmul_rn(z, z));
}
__device__ __forceinline__ unsigned int smem_u32(const void* p) {
    unsigned int a;
    asm("{ .reg .u64 t; cvta.to.shared.u64 t, %1; cvt.u32.u64 %0, t; }" : "=r"(a) : "l"(p));
    return a;
}
/* bf16x2: lo = a, hi = b */
__device__ __forceinline__ unsigned int bf16x2_of(float a, float b) {
    unsigned int r;
    asm("cvt.rn.bf16x2.f32 %0, %1, %2;" : "=r"(r) : "f"(b), "f"(a));
    return r;
}
__device__ __forceinline__ void sts32(unsigned int a, unsigned int v) {
    asm volatile("st.shared.b32 [%0], %1;" :: "r"(a), "r"(v));
}
__device__ __forceinline__ unsigned int lds32(unsigned int a) {
    unsigned int v; asm volatile("ld.shared.b32 %0, [%1];" : "=r"(v) : "r"(a)); return v;
}
__device__ __forceinline__ float ldsf(unsigned int a) {
    float v; asm volatile("ld.shared.f32 %0, [%1];" : "=f"(v) : "r"(a)); return v;
}
__device__ __forceinline__ void stsv2f(unsigned int a, float x, float y) {
    asm volatile("st.shared.v2.f32 [%0], {%1, %2};" :: "r"(a), "f"(x), "f"(y));
}
__device__ __forceinline__ void ldmat4t(unsigned int& r0, unsigned int& r1,
                                        unsigned int& r2, unsigned int& r3, unsigned int a) {
    asm volatile("ldmatrix.sync.aligned.m8n8.x4.trans.shared.b16 {%0,%1,%2,%3}, [%4];"
                 : "=r"(r0), "=r"(r1), "=r"(r2), "=r"(r3) : "r"(a));
}
__device__ __forceinline__ void mma_bf16(float* d, unsigned int a0, unsigned int a1,
                                         unsigned int a2, unsigned int a3,
                                         unsigned int b0, unsigned int b1) {
    asm volatile("mma.sync.aligned.m16n8k16.row.col.f32.bf16.bf16.f32 "
                 "{%0,%1,%2,%3}, {%4,%5,%6,%7}, {%8,%9}, {%0,%1,%2,%3};"
                 : "+f"(d[0]), "+f"(d[1]), "+f"(d[2]), "+f"(d[3])
                 : "r"(a0), "r"(a1), "r"(a2), "r"(a3), "r"(b0), "r"(b1));
}

/* ---------------- scratch: partials [row][split][14] ---------------- */
__device__ u64  d_part[L_TGT * NSPLIT * 14];
__device__ int2 d_pidx[L_TGT * NSPLIT];

__global__ void dummy1_kernel() {}
__global__ void dummy2_kernel() {}
__global__ void dummy3_kernel() {}

/* smem layout (43264 B):
   [0,6144)       shgp (argmin pairs)
   [6144,12288)   shsp (rbf pairs)
   [12288,24832)  sf: 2 sides x 16 rows x 392B (features^T bf16, row12 = ones)
   [24832,43264)  wb: 4 warps x (2 sides x 16k x 144B)  (w staging / epi scratch) */
#define OFF_SP  6144
#define OFF_SF  12288
#define SFP     392
#define OFF_WB  24832
#define WBW     4608            /* per-warp wb bytes */
#define WPITCH  144             /* w row pitch (bank-staggered, 16B-aligned) */

__global__ void __launch_bounds__(NT, 4)
pass1_kernel(const float* __restrict__ locs_left, const float* __restrict__ locs_right,
             const float* __restrict__ g1_pos, const float* __restrict__ g2_pos,
             const float* __restrict__ s1_verts, const float* __restrict__ s2_verts,
             const float* __restrict__ s1_x, const float* __restrict__ s2_x) {
    __shared__ __align__(16) unsigned char smraw[43264];
    ulonglong2* shgp = (ulonglong2*)smraw;
    ulonglong2* shsp = (ulonglong2*)(smraw + OFF_SP);
    const unsigned int sb  = smem_u32(smraw);
    const unsigned int sfL = sb + OFF_SF;
    const unsigned int sfR = sfL + 16 * SFP;
    const int tid  = threadIdx.x;
    const int wid  = tid >> 5;
    const int lane = tid & 31;
    const unsigned int wbL = sb + OFF_WB + wid * WBW;
    const unsigned int wbR = wbL + 16 * WPITCH;

    const int split = blockIdx.y;
    const int base  = split * CHUNK;
    const int cnt   = min(CHUNK, N_SRC - base);
    const int rowbase = blockIdx.x * TGB + wid * 64;
    const float INF = __int_as_float(0x7F800000);

    /* ldmatrix lane base (trans, [k][m], pitch WPITCH) */
    const unsigned int krow  = (unsigned int)((lane & 7) + ((lane >> 4) << 3));
    const unsigned int mhalf = (unsigned int)(((lane >> 3) & 1) * 8);
    const unsigned int aLb = wbL + krow * WPITCH + mhalf * 2;
    const unsigned int aRb = wbR + krow * WPITCH + mhalf * 2;
    /* w staging: thread owns adjacent targets m = 2*lane, 2*lane+1 */
    const unsigned int wsL = wbL + lane * 4;
    const unsigned int wsR = wbR + lane * 4;

    /* target constants (targets rowbase + 2*lane + u) */
    u64 txp[2], typ[2], tzp[2], sap[2];
#pragma unroll
    for (int u = 0; u < 2; u++) {
        int l = rowbase + 2 * lane + u;
        float tlx = locs_left[3*l],  tly = locs_left[3*l+1],  tlz = locs_left[3*l+2];
        float trx = locs_right[3*l], tryy = locs_right[3*l+1], trz = locs_right[3*l+2];
        txp[u] = pk(tlx, trx); typ[u] = pk(tly, tryy); tzp[u] = pk(tlz, trz);
        sap[u] = pk(norm2_ref(tlx, tly, tlz), norm2_ref(trx, tryy, trz));
    }
    const u64 NEG2P = pk(-2.0f, -2.0f);
    const u64 KNEG2 = pk(KNEG, KNEG);

    float bestL[2] = { 3.4e38f, 3.4e38f }, bestR[2] = { 3.4e38f, 3.4e38f };
    int   bidxL[2] = { 0, 0 }, bidxR[2] = { 0, 0 };
    float dL[4][2][4], dR[4][2][4];
#pragma unroll
    for (int mt = 0; mt < 4; mt++)
#pragma unroll
        for (int nt = 0; nt < 2; nt++)
#pragma unroll
            for (int e = 0; e < 4; e++) { dL[mt][nt][e] = 0.f; dR[mt][nt][e] = 0.f; }

    /* constant feature rows: 12 = ones, 13..15 = zeros (once) */
    for (int p = tid; p < TILE / 2; p += NT) {
        sts32(sfL + 12 * SFP + p * 4, 0x3F803F80u);
        sts32(sfR + 12 * SFP + p * 4, 0x3F803F80u);
#pragma unroll
        for (int q = 13; q < 16; q++) {
            sts32(sfL + q * SFP + p * 4, 0u);
            sts32(sfR + q * SFP + p * 4, 0u);
        }
    }

    for (int t = 0; t < cnt; t += TILE) {
        const int m = min(TILE, cnt - t);
        const int tbase = base + t;
        __syncthreads();
        /* ---- fill: 2 sources per thread ---- */
        for (int p = tid; p < TILE / 2; p += NT) {
            const int i0 = 2 * p;
#pragma unroll
            for (int s = 0; s < 2; s++) {
                const int i = i0 + s;
                ulonglong2 v;
                if (i < m) {
                    const int idx = tbase + i;
                    float cx = g1_pos[3*idx], cy = g1_pos[3*idx+1], cz = g1_pos[3*idx+2];
                    float dx = g2_pos[3*idx], dy = g2_pos[3*idx+1], dz = g2_pos[3*idx+2];
                    v.x = pk(cx, dx); v.y = pk(cy, dy); shgp[2*i] = v;
                    v.x = pk(cz, dz); v.y = pk(norm2_ref(cx,cy,cz), norm2_ref(dx,dy,dz));
                    shgp[2*i+1] = v;
                    float ax = s1_verts[3*idx], ay = s1_verts[3*idx+1], az = s1_verts[3*idx+2];
                    float bx = s2_verts[3*idx], by = s2_verts[3*idx+1], bz = s2_verts[3*idx+2];
                    v.x = pk(ax, bx); v.y = pk(ay, by); shsp[2*i] = v;
                    v.x = pk(az, bz); v.y = pk(norm2_ref(ax,ay,az), norm2_ref(bx,by,bz));
                    shsp[2*i+1] = v;
                } else {
                    v.x = pk(0.f, 0.f); v.y = pk(0.f, 0.f);
                    shgp[2*i] = v; shsp[2*i] = v;
                    v.y = pk(INF, INF);
                    shgp[2*i+1] = v; shsp[2*i+1] = v;
                }
            }
            /* features: pack source pair into bf16x2 rows (pad w=0 covers garbage) */
            if (i0 < m) {
                const int idx0 = tbase + i0;
                const bool full = (i0 + 1) < m;
                const float4* fa0 = (const float4*)(s1_x + 12 * idx0);
                const float4* fa1 = (const float4*)(s1_x + 12 * (idx0 + 1));
                const float4* fb0 = (const float4*)(s2_x + 12 * idx0);
                const float4* fb1 = (const float4*)(s2_x + 12 * (idx0 + 1));
#pragma unroll
                for (int q = 0; q < 3; q++) {
                    float4 a0 = fa0[q];
                    float4 a1 = full ? fa1[q] : make_float4(0.f, 0.f, 0.f, 0.f);
                    sts32(sfL + (q*4+0)*SFP + i0*2, bf16x2_of(a0.x, a1.x));
                    sts32(sfL + (q*4+1)*SFP + i0*2, bf16x2_of(a0.y, a1.y));
                    sts32(sfL + (q*4+2)*SFP + i0*2, bf16x2_of(a0.z, a1.z));
                    sts32(sfL + (q*4+3)*SFP + i0*2, bf16x2_of(a0.w, a1.w));
                    float4 b0 = fb0[q];
                    float4 b1 = full ? fb1[q] : make_float4(0.f, 0.f, 0.f, 0.f);
                    sts32(sfR + (q*4+0)*SFP + i0*2, bf16x2_of(b0.x, b1.x));
                    sts32(sfR + (q*4+1)*SFP + i0*2, bf16x2_of(b0.y, b1.y));
                    sts32(sfR + (q*4+2)*SFP + i0*2, bf16x2_of(b0.z, b1.z));
                    sts32(sfR + (q*4+3)*SFP + i0*2, bf16x2_of(b0.w, b1.w));
                }
            }
        }
        __syncthreads();

        const int nch = (m + 15) >> 4;
        for (int c = 0; c < nch; c++) {
            const int kbase = c * 16;
            __syncwarp();
            /* ---- scalar: distances, argmin, w -> staging (STS.32, conflict-free) ---- */
#pragma unroll 4
            for (int jj = 0; jj < 16; jj++) {
                const int j = kbase + jj;
                const int src = tbase + j;
                const ulonglong2 g0 = shgp[2*j], g1 = shgp[2*j+1];
                const ulonglong2 s0 = shsp[2*j], s1 = shsp[2*j+1];
                float wl[2], wr[2];
#pragma unroll
                for (int u = 0; u < 2; u++) {
                    u64 dot = fma2(tzp[u], g1.x, fma2(typ[u], g0.y, mul2(txp[u], g0.x)));
                    u64 sab = add2(sap[u], g1.y);
                    u64 d2p = fma2(dot, NEG2P, sab);
                    float d2L, d2R; upk(d2p, d2L, d2R);
                    if (d2L < bestL[u]) { bestL[u] = d2L; bidxL[u] = src; }
                    if (d2R < bestR[u]) { bestR[u] = d2R; bidxR[u] = src; }

                    u64 rdot = fma2(tzp[u], s1.x, fma2(typ[u], s0.y, mul2(txp[u], s0.x)));
                    u64 rsab = add2(sap[u], s1.y);
                    u64 r2p  = fma2(rdot, NEG2P, rsab);
                    float r2L, r2R; upk(r2p, r2L, r2R);
                    u64 sq = mul2(pk(sqrt_ap(r2L), sqrt_ap(r2R)), KNEG2);
                    float eL, eR; upk(sq, eL, eR);
                    wl[u] = ex2_ap(eL); wr[u] = ex2_ap(eR);
                }
                sts32(wsL + jj * WPITCH, bf16x2_of(wl[0], wl[1]));
                sts32(wsR + jj * WPITCH, bf16x2_of(wr[0], wr[1]));
            }
            __syncwarp();
            /* ---- B fragments ---- */
            unsigned int bL[2][2], bR[2][2];
#pragma unroll
            for (int nt = 0; nt < 2; nt++) {
                unsigned int off = ((lane >> 2) + nt*8) * SFP + (kbase + (lane & 3)*2) * 2;
                bL[nt][0] = lds32(sfL + off); bL[nt][1] = lds32(sfL + off + 16);
                bR[nt][0] = lds32(sfR + off); bR[nt][1] = lds32(sfR + off + 16);
            }
            /* ---- A fragments + MMA ---- */
#pragma unroll
            for (int mt = 0; mt < 4; mt++) {
                unsigned int a0, a1, a2, a3;
                ldmat4t(a0, a1, a2, a3, aLb + mt * 32);
                mma_bf16(dL[mt][0], a0, a1, a2, a3, bL[0][0], bL[0][1]);
                mma_bf16(dL[mt][1], a0, a1, a2, a3, bL[1][0], bL[1][1]);
                ldmat4t(a0, a1, a2, a3, aRb + mt * 32);
                mma_bf16(dR[mt][0], a0, a1, a2, a3, bR[0][0], bR[0][1]);
                mma_bf16(dR[mt][1], a0, a1, a2, a3, bR[1][0], bR[1][1]);
            }
        }
    }

    /* ---- epilogue: stage D per mt, gather per target, write partials ---- */
    const unsigned int stgL = wbL;
    const unsigned int stgR = wbL + 1024;
    const int r  = lane >> 2;
    const int cb = (lane & 3) * 2;
#pragma unroll
    for (int mt = 0; mt < 4; mt++) {
        __syncwarp();
#pragma unroll
        for (int nt = 0; nt < 2; nt++) {
            stsv2f(stgL + ((r    )*16 + nt*8 + cb)*4, dL[mt][nt][0], dL[mt][nt][1]);
            stsv2f(stgL + ((r + 8)*16 + nt*8 + cb)*4, dL[mt][nt][2], dL[mt][nt][3]);
            stsv2f(stgR + ((r    )*16 + nt*8 + cb)*4, dR[mt][nt][0], dR[mt][nt][1]);
            stsv2f(stgR + ((r + 8)*16 + nt*8 + cb)*4, dR[mt][nt][2], dR[mt][nt][3]);
        }
        __syncwarp();
        if (lane < 16) {
            const int row = rowbase + mt * 16 + lane;
            u64* pb = &d_part[(row * NSPLIT + split) * 14];
#pragma unroll
            for (int k = 0; k < 13; k++) {
                float vL = ldsf(stgL + (lane*16 + k)*4);
                float vR = ldsf(stgR + (lane*16 + k)*4);
                pb[k] = pk(vL, vR);
            }
        }
    }
#pragma unroll
    for (int u = 0; u < 2; u++) {
        const int row = rowbase + 2 * lane + u;
        const int o = row * NSPLIT + split;
        d_part[o * 14 + 13] = pk(bestL[u], bestR[u]);
        d_pidx[o] = make_int2(bidxL[u], bidxR[u]);
    }
}

/* ------------- pass2: warp per row (unchanged) ------------- */
#define P2NT 128
__global__ void __launch_bounds__(P2NT)
pass2_kernel(const float* __restrict__ g1_x, const float* __restrict__ g2_x,
             const float* __restrict__ W1, const float* __restrict__ b1,
             const float* __restrict__ W2, const float* __restrict__ b2,
             float* __restrict__ out) {
    __shared__ float sW1[2500], sb1[50], sW2[50];
    __shared__ float sx[P2NT / 32][52];
    for (int i = threadIdx.x; i < 2500; i += P2NT) sW1[i] = W1[i];
    if (threadIdx.x < 50) { sb1[threadIdx.x] = b1[threadIdx.x]; sW2[threadIdx.x] = W2[threadIdx.x]; }
    __syncthreads();

    const int w    = threadIdx.x >> 5;
    const int lane = threadIdx.x & 31;
    const int row  = blockIdx.x * (P2NT / 32) + w;

    float bestL = 3.4e38f, bestR = 3.4e38f;
    int bidxL = 0, bidxR = 0;
    float nL = 0.f, nR = 0.f;
    float aL[12], aR[12];
#pragma unroll
    for (int k = 0; k < 12; k++) { aL[k] = 0.f; aR[k] = 0.f; }

#pragma unroll
    for (int half = 0; half < 2; half++) {
        int s = lane + half * 32;
        if (s < NSPLIT) {
            const int o = row * NSPLIT + s;
            const u64* pb = &d_part[o * 14];
#pragma unroll
            for (int k = 0; k < 12; k++) {
                float xk, yk; upk(pb[k], xk, yk);
                aL[k] += xk; aR[k] += yk;
            }
            float pnL, pnR; upk(pb[12], pnL, pnR);
            nL += pnL; nR += pnR;
            float bL, bR; upk(pb[13], bL, bR);
            int2 bi = d_pidx[o];
            if (bL < bestL) { bestL = bL; bidxL = bi.x; }
            if (bR < bestR) { bestR = bR; bidxR = bi.y; }
        }
    }
#pragma unroll
    for (int m = 16; m >= 1; m >>= 1) {
        float obL = __shfl_xor_sync(0xffffffffu, bestL, m);
        int   oiL = __shfl_xor_sync(0xffffffffu, bidxL, m);
        if (obL < bestL || (obL == bestL && oiL < bidxL)) { bestL = obL; bidxL = oiL; }
        float obR = __shfl_xor_sync(0xffffffffu, bestR, m);
        int   oiR = __shfl_xor_sync(0xffffffffu, bidxR, m);
        if (obR < bestR || (obR == bestR && oiR < bidxR)) { bestR = obR; bidxR = oiR; }
        nL += __shfl_xor_sync(0xffffffffu, nL, m);
        nR += __shfl_xor_sync(0xffffffffu, nR, m);
#pragma unroll
        for (int k = 0; k < 12; k++) {
            aL[k] += __shfl_xor_sync(0xffffffffu, aL[k], m);
            aR[k] += __shfl_xor_sync(0xffffffffu, aR[k], m);
        }
    }
    nL += EPSC; nR += EPSC;

    if (lane == 0) {
        const float* gl = &g1_x[bidxL * 12];
        const float* gr = &g2_x[bidxR * 12];
        float invL = 1.f / nL, invR = 1.f / nR;
#pragma unroll
        for (int k = 0; k < 12; k++) {
            sx[w][k]      = gl[k];
            sx[w][12 + k] = aL[k] * invL;
            sx[w][25 + k] = gr[k];
            sx[w][37 + k] = aR[k] * invR;
        }
        sx[w][24] = tanhf(nL);
        sx[w][49] = tanhf(nR);
    }
    __syncwarp();

    const int j1 = lane;
    const int j2 = lane + 32;
    float h1 = sb1[j1];
    float h2 = (j2 < 50) ? sb1[j2] : 0.f;
#pragma unroll 10
    for (int i = 0; i < 50; i++) {
        float xi = sx[w][i];
        h1 = fmaf(xi, sW1[i * 50 + j1], h1);
        if (j2 < 50) h2 = fmaf(xi, sW1[i * 50 + j2], h2);
    }
    float val = (j1 < 50 ? fmaxf(h1, 0.f) * sW2[j1] : 0.f)
              + (j2 < 50 ? fmaxf(h2, 0.f) * sW2[j2] : 0.f);
#pragma unroll
    for (int m = 16; m >= 1; m >>= 1)
        val += __shfl_xor_sync(0xffffffffu, val, m);
    if (lane == 0) out[row] = val + b2[0];
}

extern "C" void kernel_launch(void* const* d_in, const int* in_sizes, int n_in,
                              void* d_out, int out_size) {
    const float* locs_left  = (const float*)d_in[0];
    const float* locs_right = (const float*)d_in[1];
    const float* g1_pos     = (const float*)d_in[2];
    const float* g1_x       = (const float*)d_in[3];
    const float* g2_pos     = (const float*)d_in[4];
    const float* g2_x       = (const float*)d_in[5];
    const float* s1_verts   = (const float*)d_in[6];
    const float* s1_x       = (const float*)d_in[7];
    const float* s2_verts   = (const float*)d_in[8];
    const float* s2_x       = (const float*)d_in[9];
    const float* W1         = (const float*)d_in[10];
    const float* b1         = (const float*)d_in[11];
    const float* W2         = (const float*)d_in[12];
    const float* b2         = (const float*)d_in[13];
    float* out = (float*)d_out;

    dummy1_kernel<<<1, 32>>>();
    dummy2_kernel<<<1, 32>>>();
    dummy3_kernel<<<1, 32>>>();
    dim3 grid1(L_TGT / TGB, NSPLIT);   /* 16 x 37 = 592 = 148 SMs * occ 4 */
    pass1_kernel<<<grid1, NT>>>(locs_left, locs_right, g1_pos, g2_pos,
                                s1_verts, s2_verts, s1_x, s2_x);
    pass2_kernel<<<L_TGT / (P2NT / 32), P2NT>>>(g1_x, g2_x, W1, b1, W2, b2, out);
}

// round 16
// speedup vs baseline: 1.4834x; 1.0322x over previous
#include <cuda_runtime.h>
#include <math.h>

#define N_SRC   40000
#define L_TGT   4096
#define NSPLIT  37
#define CHUNK   1082
#define TILE    192               /* 12 k-chunks of 16 */
#define NT      128
#define TGB     256               /* 4 warps x 64 targets */
#define KNEG    (-0.5770780163555852f)
#define EPSC    0.01f

typedef unsigned long long u64;

/* ---------------- helpers ---------------- */
__device__ __forceinline__ u64 pk(float lo, float hi) {
    u64 r; asm("mov.b64 %0, {%1, %2};" : "=l"(r) : "f"(lo), "f"(hi)); return r;
}
__device__ __forceinline__ void upk(u64 v, float& lo, float& hi) {
    asm("mov.b64 {%0, %1}, %2;" : "=f"(lo), "=f"(hi) : "l"(v));
}
__device__ __forceinline__ u64 fma2(u64 a, u64 b, u64 c) {
    u64 d; asm("fma.rn.f32x2 %0, %1, %2, %3;" : "=l"(d) : "l"(a), "l"(b), "l"(c)); return d;
}
__device__ __forceinline__ u64 mul2(u64 a, u64 b) {
    u64 d; asm("mul.rn.f32x2 %0, %1, %2;" : "=l"(d) : "l"(a), "l"(b)); return d;
}
__device__ __forceinline__ u64 add2(u64 a, u64 b) {
    u64 d; asm("add.rn.f32x2 %0, %1, %2;" : "=l"(d) : "l"(a), "l"(b)); return d;
}
__device__ __forceinline__ float sqrt_ap(float x) {
    float r; asm("sqrt.approx.f32 %0, %1;" : "=f"(r) : "f"(x)); return r;
}
__device__ __forceinline__ float ex2_ap(float x) {
    float r; asm("ex2.approx.f32 %0, %1;" : "=f"(r) : "f"(x)); return r;
}
__device__ __forceinline__ float norm2_ref(float x, float y, float z) {
    return __fadd_rn(__fadd_rn(__fmul_rn(x, x), __fmul_rn(y, y)), __fmul_rn(z, z));
}
__device__ __forceinline__ unsigned int smem_u32(const void* p) {
    unsigned int a;
    asm("{ .reg .u64 t; cvta.to.shared.u64 t, %1; cvt.u32.u64 %0, t; }" : "=r"(a) : "l"(p));
    return a;
}
/* round f32 to bf16 value (RNE), returned as f32 */
__device__ __forceinline__ float bf16f(float x) {
    unsigned int u = __float_as_uint(x);
    unsigned int r = (u + 0x7FFFu + ((u >> 16) & 1u)) & 0xFFFF0000u;
    return __uint_as_float(r);
}
/* bf16x2: lo = a, hi = b */
__device__ __forceinline__ unsigned int bf16x2_of(float a, float b) {
    unsigned int r;
    asm("cvt.rn.bf16x2.f32 %0, %1, %2;" : "=r"(r) : "f"(b), "f"(a));
    return r;
}
__device__ __forceinline__ void sts32(unsigned int a, unsigned int v) {
    asm volatile("st.shared.b32 [%0], %1;" :: "r"(a), "r"(v));
}
__device__ __forceinline__ unsigned int lds32(unsigned int a) {
    unsigned int v; asm volatile("ld.shared.b32 %0, [%1];" : "=r"(v) : "r"(a)); return v;
}
__device__ __forceinline__ float ldsf(unsigned int a) {
    float v; asm volatile("ld.shared.f32 %0, [%1];" : "=f"(v) : "r"(a)); return v;
}
__device__ __forceinline__ void stsv2f(unsigned int a, float x, float y) {
    asm volatile("st.shared.v2.f32 [%0], {%1, %2};" :: "r"(a), "f"(x), "f"(y));
}
__device__ __forceinline__ void mma_bf16(float* d, unsigned int a0, unsigned int a1,
                                         unsigned int a2, unsigned int a3,
                                         unsigned int b0, unsigned int b1) {
    asm volatile("mma.sync.aligned.m16n8k16.row.col.f32.bf16.bf16.f32 "
                 "{%0,%1,%2,%3}, {%4,%5,%6,%7}, {%8,%9}, {%0,%1,%2,%3};"
                 : "+f"(d[0]), "+f"(d[1]), "+f"(d[2]), "+f"(d[3])
                 : "r"(a0), "r"(a1), "r"(a2), "r"(a3), "r"(b0), "r"(b1));
}

/* ---------------- scratch: partials [row][split][14] ---------------- */
__device__ u64  d_part[L_TGT * NSPLIT * 14];
__device__ int2 d_pidx[L_TGT * NSPLIT];

__global__ void dummy1_kernel() {}
__global__ void dummy2_kernel() {}
__global__ void dummy3_kernel() {}

/* smem (37120 B):
   [0,6144)       shgp (argmin pairs)
   [6144,18688)   sf: 2 sides x 16 rows x 392B (features^T bf16, row12 = ones)
   [18688,37120)  sdB: 2 sides x TILE x 48B (distance-B k-vectors; epi scratch reuse) */
#define OFF_SF  6144
#define SFP     392
#define OFF_DB  18688
#define DBP     48              /* distance-B row pitch: conflict-free frag loads */

__global__ void __launch_bounds__(NT, 4)
pass1_kernel(const float* __restrict__ locs_left, const float* __restrict__ locs_right,
             const float* __restrict__ g1_pos, const float* __restrict__ g2_pos,
             const float* __restrict__ s1_verts, const float* __restrict__ s2_verts,
             const float* __restrict__ s1_x, const float* __restrict__ s2_x) {
    __shared__ __align__(16) unsigned char smraw[37120];
    ulonglong2* shgp = (ulonglong2*)smraw;
    const unsigned int sb   = smem_u32(smraw);
    const unsigned int sfL  = sb + OFF_SF;
    const unsigned int sfR  = sfL + 16 * SFP;
    const unsigned int sdBL = sb + OFF_DB;
    const unsigned int sdBR = sdBL + TILE * DBP;
    const int tid  = threadIdx.x;
    const int wid  = tid >> 5;
    const int lane = tid & 31;
    const int r    = lane >> 2;          /* frag row   */
    const int qq   = lane & 3;           /* frag quad  */

    const int split = blockIdx.y;
    const int base  = split * CHUNK;
    const int cnt   = min(CHUNK, N_SRC - base);
    const int rowbase = blockIdx.x * TGB + wid * 64;
    const float INF = __int_as_float(0x7F800000);

    /* ---- A_dist frags (constant): k-packing per col (see theory) ----
       cols: 0,1=txh,txh 2=txl 3,4=tyh,tyh 5=tyl 6,7=tzh,tzh 8=tzl 9,10=1 11=tnh 12=tnl 13..15=0 */
    unsigned int aLf[4][4], aRf[4][4];
#pragma unroll
    for (int mt = 0; mt < 4; mt++) {
#pragma unroll
        for (int h = 0; h < 2; h++) {
            const int l = rowbase + mt * 16 + r + 8 * h;
#pragma unroll
            for (int side = 0; side < 2; side++) {
                const float* lp = side ? locs_right : locs_left;
                float x = lp[3*l], y = lp[3*l+1], z = lp[3*l+2];
                float tn = x*x + y*y + z*z;
                float xh = bf16f(x), xl = x - xh;
                float yh = bf16f(y), yl = y - yh;
                float zh = bf16f(z), zl = z - zh;
                float tnh = bf16f(tn), tnl = tn - tnh;
                float lo0, lo1, hi0, hi1;
                if      (qq == 0) { lo0 = xh; lo1 = xh; hi0 = zl;  hi1 = 1.f; }
                else if (qq == 1) { lo0 = xl; lo1 = yh; hi0 = 1.f; hi1 = tnh; }
                else if (qq == 2) { lo0 = yh; lo1 = yl; hi0 = tnl; hi1 = 0.f; }
                else              { lo0 = zh; lo1 = zh; hi0 = 0.f; hi1 = 0.f; }
                unsigned int alo = bf16x2_of(lo0, lo1);
                unsigned int ahi = bf16x2_of(hi0, hi1);
                if (side == 0) { aLf[mt][h] = alo; aLf[mt][2 + h] = ahi; }
                else           { aRf[mt][h] = alo; aRf[mt][2 + h] = ahi; }
            }
        }
    }

    /* argmin target constants (targets rowbase + 2*lane + u), bit-exact path */
    u64 txp[2], typ[2], tzp[2], sap[2];
#pragma unroll
    for (int u = 0; u < 2; u++) {
        int l = rowbase + 2 * lane + u;
        float tlx = locs_left[3*l],  tly = locs_left[3*l+1],  tlz = locs_left[3*l+2];
        float trx = locs_right[3*l], tryy = locs_right[3*l+1], trz = locs_right[3*l+2];
        txp[u] = pk(tlx, trx); typ[u] = pk(tly, tryy); tzp[u] = pk(tlz, trz);
        sap[u] = pk(norm2_ref(tlx, tly, tlz), norm2_ref(trx, tryy, trz));
    }
    const u64 NEG2P = pk(-2.0f, -2.0f);

    float bestL[2] = { 3.4e38f, 3.4e38f }, bestR[2] = { 3.4e38f, 3.4e38f };
    int   bidxL[2] = { 0, 0 }, bidxR[2] = { 0, 0 };
    float dL[4][2][4], dR[4][2][4];
#pragma unroll
    for (int mt = 0; mt < 4; mt++)
#pragma unroll
        for (int nt = 0; nt < 2; nt++)
#pragma unroll
            for (int e = 0; e < 4; e++) { dL[mt][nt][e] = 0.f; dR[mt][nt][e] = 0.f; }

    /* constant feature rows: 12 = ones, 13..15 = zeros */
    for (int p = tid; p < TILE / 2; p += NT) {
        sts32(sfL + 12 * SFP + p * 4, 0x3F803F80u);
        sts32(sfR + 12 * SFP + p * 4, 0x3F803F80u);
#pragma unroll
        for (int q = 13; q < 16; q++) {
            sts32(sfL + q * SFP + p * 4, 0u);
            sts32(sfR + q * SFP + p * 4, 0u);
        }
    }

    for (int t = 0; t < cnt; t += TILE) {
        const int m = min(TILE, cnt - t);
        const int tbase = base + t;
        __syncthreads();
        /* ---- fill: argmin pairs + distance-B k-vectors + features ---- */
        for (int i = tid; i < TILE; i += NT) {
            ulonglong2 v;
            if (i < m) {
                const int idx = tbase + i;
                float cx = g1_pos[3*idx], cy = g1_pos[3*idx+1], cz = g1_pos[3*idx+2];
                float dx = g2_pos[3*idx], dy = g2_pos[3*idx+1], dz = g2_pos[3*idx+2];
                v.x = pk(cx, dx); v.y = pk(cy, dy); shgp[2*i] = v;
                v.x = pk(cz, dz); v.y = pk(norm2_ref(cx,cy,cz), norm2_ref(dx,dy,dz));
                shgp[2*i+1] = v;
#pragma unroll
                for (int side = 0; side < 2; side++) {
                    const float* sp = side ? s2_verts : s1_verts;
                    const unsigned int db = (side ? sdBR : sdBL) + i * DBP;
                    float x = sp[3*idx], y = sp[3*idx+1], z = sp[3*idx+2];
                    float sn = x*x + y*y + z*z;
                    float ux = -2.f*x, uy = -2.f*y, uz = -2.f*z;
                    float uxh = bf16f(ux), uxl = ux - uxh;
                    float uyh = bf16f(uy), uyl = uy - uyh;
                    float uzh = bf16f(uz), uzl = uz - uzh;
                    float snh = bf16f(sn), snl = sn - snh;
                    sts32(db + 0,  bf16x2_of(uxh, uxl));
                    sts32(db + 4,  bf16x2_of(uxh, uyh));
                    sts32(db + 8,  bf16x2_of(uyl, uyh));
                    sts32(db + 12, bf16x2_of(uzh, uzl));
                    sts32(db + 16, bf16x2_of(uzh, snh));
                    sts32(db + 20, bf16x2_of(snl, 1.f));
                    sts32(db + 24, bf16x2_of(1.f, 0.f));
                    sts32(db + 28, 0u);
                }
                const float4* fa = (const float4*)(s1_x + 12 * idx);
                const float4* fb = (const float4*)(s2_x + 12 * idx);
#pragma unroll
                for (int q = 0; q < 3; q++) {
                    float4 a = fa[q], b = fb[q];
                    unsigned short ha0, ha1, ha2, ha3;
                    asm("cvt.rn.bf16.f32 %0, %1;" : "=h"(ha0) : "f"(a.x));
                    asm("cvt.rn.bf16.f32 %0, %1;" : "=h"(ha1) : "f"(a.y));
                    asm("cvt.rn.bf16.f32 %0, %1;" : "=h"(ha2) : "f"(a.z));
                    asm("cvt.rn.bf16.f32 %0, %1;" : "=h"(ha3) : "f"(a.w));
                    asm volatile("st.shared.b16 [%0], %1;" :: "r"(sfL + (q*4+0)*SFP + i*2), "h"(ha0));
                    asm volatile("st.shared.b16 [%0], %1;" :: "r"(sfL + (q*4+1)*SFP + i*2), "h"(ha1));
                    asm volatile("st.shared.b16 [%0], %1;" :: "r"(sfL + (q*4+2)*SFP + i*2), "h"(ha2));
                    asm volatile("st.shared.b16 [%0], %1;" :: "r"(sfL + (q*4+3)*SFP + i*2), "h"(ha3));
                    asm("cvt.rn.bf16.f32 %0, %1;" : "=h"(ha0) : "f"(b.x));
                    asm("cvt.rn.bf16.f32 %0, %1;" : "=h"(ha1) : "f"(b.y));
                    asm("cvt.rn.bf16.f32 %0, %1;" : "=h"(ha2) : "f"(b.z));
                    asm("cvt.rn.bf16.f32 %0, %1;" : "=h"(ha3) : "f"(b.w));
                    asm volatile("st.shared.b16 [%0], %1;" :: "r"(sfR + (q*4+0)*SFP + i*2), "h"(ha0));
                    asm volatile("st.shared.b16 [%0], %1;" :: "r"(sfR + (q*4+1)*SFP + i*2), "h"(ha1));
                    asm volatile("st.shared.b16 [%0], %1;" :: "r"(sfR + (q*4+2)*SFP + i*2), "h"(ha2));
                    asm volatile("st.shared.b16 [%0], %1;" :: "r"(sfR + (q*4+3)*SFP + i*2), "h"(ha3));
                }
            } else {
                /* pad: argmin INF; distance-B -> d2 = 1e20 -> w = 0 */
                v.x = pk(0.f, 0.f); v.y = pk(0.f, 0.f);
                shgp[2*i] = v;
                v.y = pk(INF, INF);
                shgp[2*i+1] = v;
#pragma unroll
                for (int side = 0; side < 2; side++) {
                    const unsigned int db = (side ? sdBR : sdBL) + i * DBP;
#pragma unroll
                    for (int q = 0; q < 5; q++) sts32(db + q*4, 0u);
                    sts32(db + 16, bf16x2_of(0.f, 1e20f));   /* snh = 1e20 */
                    sts32(db + 20, bf16x2_of(0.f, 1.f));
                    sts32(db + 24, bf16x2_of(1.f, 0.f));
                    sts32(db + 28, 0u);
                }
            }
        }
        __syncthreads();

        const int nch = (m + 15) >> 4;
        for (int c = 0; c < nch; c++) {
            const int kbase = c * 16;
            /* ---- scalar argmin over 16 sources (bit-exact) ---- */
#pragma unroll 4
            for (int jj = 0; jj < 16; jj++) {
                const int j = kbase + jj;
                const int src = tbase + j;
                const ulonglong2 g0 = shgp[2*j], g1 = shgp[2*j+1];
#pragma unroll
                for (int u = 0; u < 2; u++) {
                    u64 dot = fma2(tzp[u], g1.x, fma2(typ[u], g0.y, mul2(txp[u], g0.x)));
                    u64 sab = add2(sap[u], g1.y);
                    u64 d2p = fma2(dot, NEG2P, sab);
                    float d2L, d2R; upk(d2p, d2L, d2R);
                    if (d2L < bestL[u]) { bestL[u] = d2L; bidxL[u] = src; }
                    if (d2R < bestR[u]) { bestR[u] = d2R; bidxR[u] = src; }
                }
            }
            /* ---- distance-B frags (48B pitch: conflict-free) ---- */
            unsigned int dbL[2][2], dbR[2][2];
#pragma unroll
            for (int nt = 0; nt < 2; nt++) {
                const unsigned int off = (kbase + nt*8 + r) * DBP + qq * 4;
                dbL[nt][0] = lds32(sdBL + off); dbL[nt][1] = lds32(sdBL + off + 16);
                dbR[nt][0] = lds32(sdBR + off); dbR[nt][1] = lds32(sdBR + off + 16);
            }
            /* ---- feature-B frags ---- */
            unsigned int fbL[2][2], fbR[2][2];
#pragma unroll
            for (int nt = 0; nt < 2; nt++) {
                unsigned int off = (r + nt*8) * SFP + (kbase + qq*2) * 2;
                fbL[nt][0] = lds32(sfL + off); fbL[nt][1] = lds32(sfL + off + 16);
                fbR[nt][0] = lds32(sfR + off); fbR[nt][1] = lds32(sfR + off + 16);
            }
            /* ---- per mt: distance MMA -> w -> feature MMA ---- */
#pragma unroll
            for (int mt = 0; mt < 4; mt++) {
                float dda[4] = {0.f, 0.f, 0.f, 0.f};
                float ddb[4] = {0.f, 0.f, 0.f, 0.f};
                mma_bf16(dda, aLf[mt][0], aLf[mt][1], aLf[mt][2], aLf[mt][3], dbL[0][0], dbL[0][1]);
                mma_bf16(ddb, aLf[mt][0], aLf[mt][1], aLf[mt][2], aLf[mt][3], dbL[1][0], dbL[1][1]);
                unsigned int wa0 = bf16x2_of(ex2_ap(KNEG * sqrt_ap(fmaxf(dda[0], 0.f))),
                                             ex2_ap(KNEG * sqrt_ap(fmaxf(dda[1], 0.f))));
                unsigned int wa1 = bf16x2_of(ex2_ap(KNEG * sqrt_ap(fmaxf(dda[2], 0.f))),
                                             ex2_ap(KNEG * sqrt_ap(fmaxf(dda[3], 0.f))));
                unsigned int wa2 = bf16x2_of(ex2_ap(KNEG * sqrt_ap(fmaxf(ddb[0], 0.f))),
                                             ex2_ap(KNEG * sqrt_ap(fmaxf(ddb[1], 0.f))));
                unsigned int wa3 = bf16x2_of(ex2_ap(KNEG * sqrt_ap(fmaxf(ddb[2], 0.f))),
                                             ex2_ap(KNEG * sqrt_ap(fmaxf(ddb[3], 0.f))));
                mma_bf16(dL[mt][0], wa0, wa1, wa2, wa3, fbL[0][0], fbL[0][1]);
                mma_bf16(dL[mt][1], wa0, wa1, wa2, wa3, fbL[1][0], fbL[1][1]);

                float dea[4] = {0.f, 0.f, 0.f, 0.f};
                float deb[4] = {0.f, 0.f, 0.f, 0.f};
                mma_bf16(dea, aRf[mt][0], aRf[mt][1], aRf[mt][2], aRf[mt][3], dbR[0][0], dbR[0][1]);
                mma_bf16(deb, aRf[mt][0], aRf[mt][1], aRf[mt][2], aRf[mt][3], dbR[1][0], dbR[1][1]);
                wa0 = bf16x2_of(ex2_ap(KNEG * sqrt_ap(fmaxf(dea[0], 0.f))),
                                ex2_ap(KNEG * sqrt_ap(fmaxf(dea[1], 0.f))));
                wa1 = bf16x2_of(ex2_ap(KNEG * sqrt_ap(fmaxf(dea[2], 0.f))),
                                ex2_ap(KNEG * sqrt_ap(fmaxf(dea[3], 0.f))));
                wa2 = bf16x2_of(ex2_ap(KNEG * sqrt_ap(fmaxf(deb[0], 0.f))),
                                ex2_ap(KNEG * sqrt_ap(fmaxf(deb[1], 0.f))));
                wa3 = bf16x2_of(ex2_ap(KNEG * sqrt_ap(fmaxf(deb[2], 0.f))),
                                ex2_ap(KNEG * sqrt_ap(fmaxf(deb[3], 0.f))));
                mma_bf16(dR[mt][0], wa0, wa1, wa2, wa3, fbR[0][0], fbR[0][1]);
                mma_bf16(dR[mt][1], wa0, wa1, wa2, wa3, fbR[1][0], fbR[1][1]);
            }
        }
    }

    /* ---- epilogue (scratch reuses sdB region; must sync first) ---- */
    __syncthreads();
    const unsigned int stgL = sdBL + wid * 2048;
    const unsigned int stgR = stgL + 1024;
    const int cb = qq * 2;
#pragma unroll
    for (int mt = 0; mt < 4; mt++) {
        __syncwarp();
#pragma unroll
        for (int nt = 0; nt < 2; nt++) {
            stsv2f(stgL + ((r    )*16 + nt*8 + cb)*4, dL[mt][nt][0], dL[mt][nt][1]);
            stsv2f(stgL + ((r + 8)*16 + nt*8 + cb)*4, dL[mt][nt][2], dL[mt][nt][3]);
            stsv2f(stgR + ((r    )*16 + nt*8 + cb)*4, dR[mt][nt][0], dR[mt][nt][1]);
            stsv2f(stgR + ((r + 8)*16 + nt*8 + cb)*4, dR[mt][nt][2], dR[mt][nt][3]);
        }
        __syncwarp();
        if (lane < 16) {
            const int row = rowbase + mt * 16 + lane;
            u64* pb = &d_part[(row * NSPLIT + split) * 14];
#pragma unroll
            for (int k = 0; k < 13; k++) {
                float vL = ldsf(stgL + (lane*16 + k)*4);
                float vR = ldsf(stgR + (lane*16 + k)*4);
                pb[k] = pk(vL, vR);
            }
        }
    }
#pragma unroll
    for (int u = 0; u < 2; u++) {
        const int row = rowbase + 2 * lane + u;
        const int o = row * NSPLIT + split;
        d_part[o * 14 + 13] = pk(bestL[u], bestR[u]);
        d_pidx[o] = make_int2(bidxL[u], bidxR[u]);
    }
}

/* ------------- pass2: warp per row (unchanged) ------------- */
#define P2NT 128
__global__ void __launch_bounds__(P2NT)
pass2_kernel(const float* __restrict__ g1_x, const float* __restrict__ g2_x,
             const float* __restrict__ W1, const float* __restrict__ b1,
             const float* __restrict__ W2, const float* __restrict__ b2,
             float* __restrict__ out) {
    __shared__ float sW1[2500], sb1[50], sW2[50];
    __shared__ float sx[P2NT / 32][52];
    for (int i = threadIdx.x; i < 2500; i += P2NT) sW1[i] = W1[i];
    if (threadIdx.x < 50) { sb1[threadIdx.x] = b1[threadIdx.x]; sW2[threadIdx.x] = W2[threadIdx.x]; }
    __syncthreads();

    const int w    = threadIdx.x >> 5;
    const int lane = threadIdx.x & 31;
    const int row  = blockIdx.x * (P2NT / 32) + w;

    float bestL = 3.4e38f, bestR = 3.4e38f;
    int bidxL = 0, bidxR = 0;
    float nL = 0.f, nR = 0.f;
    float aL[12], aR[12];
#pragma unroll
    for (int k = 0; k < 12; k++) { aL[k] = 0.f; aR[k] = 0.f; }

#pragma unroll
    for (int half = 0; half < 2; half++) {
        int s = lane + half * 32;
        if (s < NSPLIT) {
            const int o = row * NSPLIT + s;
            const u64* pb = &d_part[o * 14];
#pragma unroll
            for (int k = 0; k < 12; k++) {
                float xk, yk; upk(pb[k], xk, yk);
                aL[k] += xk; aR[k] += yk;
            }
            float pnL, pnR; upk(pb[12], pnL, pnR);
            nL += pnL; nR += pnR;
            float bL, bR; upk(pb[13], bL, bR);
            int2 bi = d_pidx[o];
            if (bL < bestL) { bestL = bL; bidxL = bi.x; }
            if (bR < bestR) { bestR = bR; bidxR = bi.y; }
        }
    }
#pragma unroll
    for (int m = 16; m >= 1; m >>= 1) {
        float obL = __shfl_xor_sync(0xffffffffu, bestL, m);
        int   oiL = __shfl_xor_sync(0xffffffffu, bidxL, m);
        if (obL < bestL || (obL == bestL && oiL < bidxL)) { bestL = obL; bidxL = oiL; }
        float obR = __shfl_xor_sync(0xffffffffu, bestR, m);
        int   oiR = __shfl_xor_sync(0xffffffffu, bidxR, m);
        if (obR < bestR || (obR == bestR && oiR < bidxR)) { bestR = obR; bidxR = oiR; }
        nL += __shfl_xor_sync(0xffffffffu, nL, m);
        nR += __shfl_xor_sync(0xffffffffu, nR, m);
#pragma unroll
        for (int k = 0; k < 12; k++) {
            aL[k] += __shfl_xor_sync(0xffffffffu, aL[k], m);
            aR[k] += __shfl_xor_sync(0xffffffffu, aR[k], m);
        }
    }
    nL += EPSC; nR += EPSC;

    if (lane == 0) {
        const float* gl = &g1_x[bidxL * 12];
        const float* gr = &g2_x[bidxR * 12];
        float invL = 1.f / nL, invR = 1.f / nR;
#pragma unroll
        for (int k = 0; k < 12; k++) {
            sx[w][k]      = gl[k];
            sx[w][12 + k] = aL[k] * invL;
            sx[w][25 + k] = gr[k];
            sx[w][37 + k] = aR[k] * invR;
        }
        sx[w][24] = tanhf(nL);
        sx[w][49] = tanhf(nR);
    }
    __syncwarp();

    const int j1 = lane;
    const int j2 = lane + 32;
    float h1 = sb1[j1];
    float h2 = (j2 < 50) ? sb1[j2] : 0.f;
#pragma unroll 10
    for (int i = 0; i < 50; i++) {
        float xi = sx[w][i];
        h1 = fmaf(xi, sW1[i * 50 + j1], h1);
        if (j2 < 50) h2 = fmaf(xi, sW1[i * 50 + j2], h2);
    }
    float val = (j1 < 50 ? fmaxf(h1, 0.f) * sW2[j1] : 0.f)
              + (j2 < 50 ? fmaxf(h2, 0.f) * sW2[j2] : 0.f);
#pragma unroll
    for (int m = 16; m >= 1; m >>= 1)
        val += __shfl_xor_sync(0xffffffffu, val, m);
    if (lane == 0) out[row] = val + b2[0];
}

extern "C" void kernel_launch(void* const* d_in, const int* in_sizes, int n_in,
                              void* d_out, int out_size) {
    const float* locs_left  = (const float*)d_in[0];
    const float* locs_right = (const float*)d_in[1];
    const float* g1_pos     = (const float*)d_in[2];
    const float* g1_x       = (const float*)d_in[3];
    const float* g2_pos     = (const float*)d_in[4];
    const float* g2_x       = (const float*)d_in[5];
    const float* s1_verts   = (const float*)d_in[6];
    const float* s1_x       = (const float*)d_in[7];
    const float* s2_verts   = (const float*)d_in[8];
    const float* s2_x       = (const float*)d_in[9];
    const float* W1         = (const float*)d_in[10];
    const float* b1         = (const float*)d_in[11];
    const float* W2         = (const float*)d_in[12];
    const float* b2         = (const float*)d_in[13];
    float* out = (float*)d_out;

    dummy1_kernel<<<1, 32>>>();
    dummy2_kernel<<<1, 32>>>();
    dummy3_kernel<<<1, 32>>>();
    dim3 grid1(L_TGT / TGB, NSPLIT);   /* 16 x 37 = 592 = 148 SMs * occ 4 */
    pass1_kernel<<<grid1, NT>>>(locs_left, locs_right, g1_pos, g2_pos,
                                s1_verts, s2_verts, s1_x, s2_x);
    pass2_kernel<<<L_TGT / (P2NT / 32), P2NT>>>(g1_x, g2_x, W1, b1, W2, b2, out);
}